// round 1
// baseline (speedup 1.0000x reference)
#include <cuda_runtime.h>
#include <math.h>

#define IDIM 128
#define HDIM 1024
#define CDIM 256
#define NIT  4
#define NTOK 2048
#define G    4            // tokens per block
#define NT   256          // threads per block
#define NBLK (NTOK / G)   // 512 blocks
#define IGNORE_OUT 10000.0f

// scratch (no allocations allowed)
__device__ float g_partS[NBLK];
__device__ int   g_partC[NBLK];

__global__ __launch_bounds__(NT)
void fwd_kernel(const float* __restrict__ x,  const float* __restrict__ y,
                const float* __restrict__ w1, const float* __restrict__ b1,
                const float* __restrict__ w2, const float* __restrict__ b2)
{
    __shared__ __align__(16) float sx [G][IDIM];  // x_res
    __shared__ __align__(16) float sy [G][IDIM];  // y_res
    __shared__ __align__(16) float sxa[G][IDIM];  // x_attn
    __shared__ __align__(16) float sh [G][CDIM];  // h (active block)
    __shared__ __align__(16) float sye[G][IDIM];  // half-sum scratch for y_ele
    __shared__ unsigned char smsk[G][IDIM];       // seq_mask from ORIGINAL y
    __shared__ float redf[8];
    __shared__ int   redi[8];
    __shared__ float s_ny[G];
    __shared__ int   s_idx[G];

    const int tid  = threadIdx.x;
    const int blk  = blockIdx.x;
    const int tok0 = blk * G;

    // ---- load tokens + mask ----
    int cnt = 0;
    for (int k = tid; k < G * IDIM; k += NT) {
        int g = k >> 7, d = k & 127;
        sx[g][d] = x[(tok0 + g) * IDIM + d];
        float yv = y[(tok0 + g) * IDIM + d];
        sy[g][d] = yv;
        unsigned char m = (yv == IGNORE_OUT) ? 1 : 0;
        smsk[g][d] = m;
        cnt += 1 - (int)m;
    }
    // deterministic count reduction
    for (int o = 16; o > 0; o >>= 1) cnt += __shfl_xor_sync(0xffffffffu, cnt, o);
    if ((tid & 31) == 0) redi[tid >> 5] = cnt;
    __syncthreads();
    if (tid == 0) {
        int c = 0;
        for (int w = 0; w < 8; w++) c += redi[w];
        g_partC[blk] = c;
    }
    __syncthreads();

    const int g    = tid >> 6;   // token group (64 threads each)
    const int tt   = tid & 63;
    const int lane = tid & 31;
    const int wid  = tid >> 5;

    float lossAcc = 0.f;

    for (int it = 0; it < NIT; ++it) {
        // ================= ||y_res|| per token =================
        {
            float a = sy[g][tt], b = sy[g][tt + 64];
            float v = a * a + b * b;
            for (int o = 16; o > 0; o >>= 1) v += __shfl_xor_sync(0xffffffffu, v, o);
            if (lane == 0) redf[wid] = v;
            __syncthreads();
            if (tt == 0) s_ny[g] = sqrtf(redf[2 * g] + redf[2 * g + 1]);
            __syncthreads();
        }
        const float ny = s_ny[g];

        // ================= sliding cosine corr + first-max argmax =================
        {
            float bv = -1e30f; int bi = 0;
            #pragma unroll
            for (int k = 0; k < 4; k++) {
                int s = tt + 64 * k;
                if (s < 2 * IDIM - 1) {
                    int lo = s - 127; if (lo < 0) lo = 0;
                    int hi = s;       if (hi > 127) hi = 127;
                    const int yo = 127 - s;
                    float num = 0.f, dx = 0.f;
                    for (int j = lo; j <= hi; j++) {
                        float xv = sx[g][j];
                        num += sy[g][j + yo] * xv;
                        dx  += xv * xv;
                    }
                    float den = ny * sqrtf(dx);
                    float sim = (den == 0.f) ? 0.f : (num / den);
                    if (sim > bv) { bv = sim; bi = s; }   // ascending s -> keeps first max
                }
            }
            for (int o = 16; o > 0; o >>= 1) {
                float ov = __shfl_xor_sync(0xffffffffu, bv, o);
                int   oi = __shfl_xor_sync(0xffffffffu, bi, o);
                if (ov > bv || (ov == bv && oi < bi)) { bv = ov; bi = oi; }
            }
            if (lane == 0) { redf[wid] = bv; redi[wid] = bi; }
            __syncthreads();
            if (tt == 0) {
                float v0 = redf[2 * g];     int i0 = redi[2 * g];
                float v1 = redf[2 * g + 1]; int i1 = redi[2 * g + 1];
                s_idx[g] = (v1 > v0 || (v1 == v0 && i1 < i0)) ? i1 : i0;
            }
            __syncthreads();
        }
        const int off = s_idx[g] - 127;

        // ================= x_aug, softmax attention, x_attn =================
        {
            int d0 = tt, d1 = tt + 64;
            int p0 = d0 + off, p1 = d1 + off;
            float xa0 = (p0 >= 0 && p0 < IDIM) ? sx[g][p0] : 0.f;
            float xa1 = (p1 >= 0 && p1 < IDIM) ? sx[g][p1] : 0.f;
            float z0 = xa0 * sy[g][d0];
            float z1 = xa1 * sy[g][d1];
            float m = fmaxf(z0, z1);
            for (int o = 16; o > 0; o >>= 1) m = fmaxf(m, __shfl_xor_sync(0xffffffffu, m, o));
            if (lane == 0) redf[wid] = m;
            __syncthreads();
            m = fmaxf(redf[2 * g], redf[2 * g + 1]);
            __syncthreads();
            float e0 = expf(z0 - m), e1 = expf(z1 - m);
            float se = e0 + e1;
            for (int o = 16; o > 0; o >>= 1) se += __shfl_xor_sync(0xffffffffu, se, o);
            if (lane == 0) redf[wid] = se;
            __syncthreads();
            se = redf[2 * g] + redf[2 * g + 1];
            sxa[g][d0] = xa0 * (e0 / se);
            sxa[g][d1] = xa1 * (e1 / se);
            __syncthreads();
        }

        // ================= x_ele (reverse shift) and x_res update =================
        {
            int d0 = tt, d1 = tt + 64;
            int q0 = d0 - off, q1 = d1 - off;
            float xe0 = (q0 >= 0 && q0 < IDIM) ? sxa[g][q0] : 0.f;
            float xe1 = (q1 >= 0 && q1 < IDIM) ? sxa[g][q1] : 0.f;
            sx[g][d0] -= xe0;
            sx[g][d1] -= xe1;
            // sx not read again until next iteration (syncs in between)
        }

        // ================= MLP layer 1 : h[c] over active block =================
        {
            int ch = it * CDIM + tid;  // 256 channels, one per thread
            const float4* w1v = (const float4*)(w1 + ch * IDIM);
            float acc0 = 0.f, acc1 = 0.f, acc2 = 0.f, acc3 = 0.f;
            const float4* xa0v = (const float4*)sxa[0];
            const float4* xa1v = (const float4*)sxa[1];
            const float4* xa2v = (const float4*)sxa[2];
            const float4* xa3v = (const float4*)sxa[3];
            #pragma unroll 4
            for (int q = 0; q < IDIM / 4; q++) {
                float4 w  = w1v[q];
                float4 a0 = xa0v[q], a1 = xa1v[q], a2 = xa2v[q], a3 = xa3v[q];
                acc0 += w.x * a0.x + w.y * a0.y + w.z * a0.z + w.w * a0.w;
                acc1 += w.x * a1.x + w.y * a1.y + w.z * a1.z + w.w * a1.w;
                acc2 += w.x * a2.x + w.y * a2.y + w.z * a2.z + w.w * a2.w;
                acc3 += w.x * a3.x + w.y * a3.y + w.z * a3.z + w.w * a3.w;
            }
            float bb = b1[ch];
            sh[0][tid] = acc0 + bb;
            sh[1][tid] = acc1 + bb;
            sh[2][tid] = acc2 + bb;
            sh[3][tid] = acc3 + bb;
            __syncthreads();
        }

        // ================= MLP layer 2 + loss + y_res update =================
        {
            int o    = tid & 127;
            int half = tid >> 7;
            const float4* w2v = (const float4*)(w2 + o * HDIM + it * CDIM + half * 128);
            const float4* h0v = (const float4*)(&sh[0][half * 128]);
            const float4* h1v = (const float4*)(&sh[1][half * 128]);
            const float4* h2v = (const float4*)(&sh[2][half * 128]);
            const float4* h3v = (const float4*)(&sh[3][half * 128]);
            float acc0 = 0.f, acc1 = 0.f, acc2 = 0.f, acc3 = 0.f;
            #pragma unroll 4
            for (int q = 0; q < 32; q++) {
                float4 w  = w2v[q];
                float4 h0 = h0v[q], h1 = h1v[q], h2 = h2v[q], h3 = h3v[q];
                acc0 += w.x * h0.x + w.y * h0.y + w.z * h0.z + w.w * h0.w;
                acc1 += w.x * h1.x + w.y * h1.y + w.z * h1.z + w.w * h1.w;
                acc2 += w.x * h2.x + w.y * h2.y + w.z * h2.z + w.w * h2.w;
                acc3 += w.x * h3.x + w.y * h3.y + w.z * h3.z + w.w * h3.w;
            }
            if (half == 1) {
                sye[0][o] = acc0; sye[1][o] = acc1; sye[2][o] = acc2; sye[3][o] = acc3;
            }
            __syncthreads();
            if (half == 0) {
                float bb = b2[o];
                float accs[4] = {acc0, acc1, acc2, acc3};
                #pragma unroll
                for (int gg = 0; gg < G; gg++) {
                    float ye = accs[gg] + sye[gg][o] + bb;
                    float yr = sy[gg][o];
                    float d  = ye - yr;
                    if (!smsk[gg][o]) lossAcc += d * d;
                    sy[gg][o] = yr - ye;
                }
            }
            __syncthreads();
        }
    }

    // ---- deterministic per-block loss reduction ----
    for (int o = 16; o > 0; o >>= 1) lossAcc += __shfl_xor_sync(0xffffffffu, lossAcc, o);
    if (lane == 0) redf[wid] = lossAcc;
    __syncthreads();
    if (tid == 0) {
        float s = 0.f;
        for (int w = 0; w < 8; w++) s += redf[w];
        g_partS[blk] = s;
    }
}

__global__ void fin_kernel(float* __restrict__ out)
{
    __shared__ float rf[16];
    __shared__ int   rc[16];
    int tid = threadIdx.x;           // NBLK = 512 threads
    float s = g_partS[tid];
    int   c = g_partC[tid];
    for (int o = 16; o > 0; o >>= 1) {
        s += __shfl_xor_sync(0xffffffffu, s, o);
        c += __shfl_xor_sync(0xffffffffu, c, o);
    }
    if ((tid & 31) == 0) { rf[tid >> 5] = s; rc[tid >> 5] = c; }
    __syncthreads();
    if (tid == 0) {
        float S = 0.f; int C = 0;
        for (int w = 0; w < 16; w++) { S += rf[w]; C += rc[w]; }
        out[0] = S / (4.0f * (float)C);   // mean over NIT of (sum_sq / denom)
    }
}

extern "C" void kernel_launch(void* const* d_in, const int* in_sizes, int n_in,
                              void* d_out, int out_size)
{
    const float* x  = (const float*)d_in[0];
    const float* y  = (const float*)d_in[1];
    const float* w1 = (const float*)d_in[2];
    const float* b1 = (const float*)d_in[3];
    const float* w2 = (const float*)d_in[4];
    const float* b2 = (const float*)d_in[5];
    fwd_kernel<<<NBLK, NT>>>(x, y, w1, b1, w2, b2);
    fin_kernel<<<1, NBLK>>>((float*)d_out);
}

// round 2
// speedup vs baseline: 1.2028x; 1.2028x over previous
#include <cuda_runtime.h>
#include <math.h>

#define IDIM 128
#define HDIM 1024
#define CDIM 256
#define NIT  4
#define NTOK 2048
#define G    4            // tokens per block
#define NT   256          // threads per block
#define NBLK (NTOK / G)   // 512 blocks
#define IGNORE_OUT 10000.0f

// ---- device scratch (no allocations allowed) ----
__device__ float g_w1t[IDIM * HDIM];   // w1t[d*HDIM + h] = w1[h*IDIM + d]
__device__ float g_w2t[HDIM * IDIM];   // w2t[k*IDIM + o] = w2[o*HDIM + k]
__device__ float g_partS[NBLK];
__device__ int   g_partC[NBLK];
__device__ unsigned int g_ticket;      // zero-init, reset by last block

// ================= weight transposes (coalesced tiled) =================
__global__ __launch_bounds__(256) void transpose_w1(const float* __restrict__ w1)
{
    __shared__ float tile[32][33];
    int c0 = blockIdx.x * 32, r0 = blockIdx.y * 32;   // src: HDIM x IDIM
    int tx = threadIdx.x, ty = threadIdx.y;
    #pragma unroll
    for (int i = 0; i < 32; i += 8)
        tile[ty + i][tx] = w1[(r0 + ty + i) * IDIM + c0 + tx];
    __syncthreads();
    #pragma unroll
    for (int i = 0; i < 32; i += 8)
        g_w1t[(c0 + ty + i) * HDIM + r0 + tx] = tile[tx][ty + i];
}

__global__ __launch_bounds__(256) void transpose_w2(const float* __restrict__ w2)
{
    __shared__ float tile[32][33];
    int c0 = blockIdx.x * 32, r0 = blockIdx.y * 32;   // src: IDIM x HDIM
    int tx = threadIdx.x, ty = threadIdx.y;
    #pragma unroll
    for (int i = 0; i < 32; i += 8)
        tile[ty + i][tx] = w2[(r0 + ty + i) * HDIM + c0 + tx];
    __syncthreads();
    #pragma unroll
    for (int i = 0; i < 32; i += 8)
        g_w2t[(c0 + ty + i) * IDIM + r0 + tx] = tile[tx][ty + i];
}

// ================= fused forward =================
__global__ __launch_bounds__(NT)
void fwd_kernel(const float* __restrict__ x,  const float* __restrict__ y,
                const float* __restrict__ b1, const float* __restrict__ b2,
                float* __restrict__ out)
{
    __shared__ __align__(16) float sx [G][IDIM];      // x_res
    __shared__ __align__(16) float sy [G][IDIM];      // y_res
    __shared__ __align__(16) float sxa[G][IDIM + 4];  // x_attn (padded: bank-spread)
    __shared__ __align__(16) float sh [G][CDIM + 4];  // h active block (padded)
    __shared__ __align__(16) float sye[G][IDIM + 4];  // half-1 partial of y_ele
    __shared__ unsigned char smsk[G][IDIM];           // seq_mask from ORIGINAL y
    __shared__ float redf[8];
    __shared__ int   redi[8];
    __shared__ float s_ny[G];
    __shared__ int   s_idx[G];
    __shared__ int   sIsLast;

    const int tid  = threadIdx.x;
    const int blk  = blockIdx.x;
    const int tok0 = blk * G;

    // ---- load tokens + mask + unmasked count ----
    int cnt = 0;
    for (int k = tid; k < G * IDIM; k += NT) {
        int g = k >> 7, d = k & 127;
        sx[g][d] = x[(tok0 + g) * IDIM + d];
        float yv = y[(tok0 + g) * IDIM + d];
        sy[g][d] = yv;
        unsigned char m = (yv == IGNORE_OUT) ? 1 : 0;
        smsk[g][d] = m;
        cnt += 1 - (int)m;
    }
    for (int o = 16; o > 0; o >>= 1) cnt += __shfl_xor_sync(0xffffffffu, cnt, o);
    if ((tid & 31) == 0) redi[tid >> 5] = cnt;
    __syncthreads();
    if (tid == 0) {
        int c = 0;
        for (int w = 0; w < 8; w++) c += redi[w];
        g_partC[blk] = c;
    }
    __syncthreads();

    const int g64  = tid >> 6;   // token for 64-thread-per-token phases
    const int tt   = tid & 63;
    const int lane = tid & 31;
    const int wid  = tid >> 5;

    // MLP1 mapping: 4 channels x 1 token per thread
    const int m1_tc = tid >> 2;      // channel group 0..63
    const int m1_g  = tid & 3;       // token
    // MLP2 mapping: 4 outputs x 1 token x half-of-k per thread
    const int m2_half = tid >> 7;
    const int m2_og   = (tid & 127) >> 2;  // output group 0..31
    const int m2_g    = tid & 3;           // token

    float lossAcc = 0.f;

    for (int it = 0; it < NIT; ++it) {
        // ================= ||y_res|| per token =================
        {
            float a = sy[g64][tt], b = sy[g64][tt + 64];
            float v = a * a + b * b;
            for (int o = 16; o > 0; o >>= 1) v += __shfl_xor_sync(0xffffffffu, v, o);
            if (lane == 0) redf[wid] = v;
            __syncthreads();
            if (tt == 0) s_ny[g64] = sqrtf(redf[2 * g64] + redf[2 * g64 + 1]);
            __syncthreads();
        }
        const float ny = s_ny[g64];

        // ================= sliding cosine corr + first-max argmax =================
        {
            float bv = -1e30f; int bi = 0;
            #pragma unroll
            for (int k = 0; k < 4; k++) {
                int s = tt + 64 * k;
                if (s < 2 * IDIM - 1) {
                    int lo = s - 127; if (lo < 0) lo = 0;
                    int hi = s;       if (hi > 127) hi = 127;
                    const int yo = 127 - s;
                    float num = 0.f, dx = 0.f;
                    for (int j = lo; j <= hi; j++) {
                        float xv = sx[g64][j];
                        num += sy[g64][j + yo] * xv;
                        dx  += xv * xv;
                    }
                    float den = ny * sqrtf(dx);
                    float sim = (den == 0.f) ? 0.f : (num / den);
                    if (sim > bv) { bv = sim; bi = s; }   // ascending s keeps first max
                }
            }
            for (int o = 16; o > 0; o >>= 1) {
                float ov = __shfl_xor_sync(0xffffffffu, bv, o);
                int   oi = __shfl_xor_sync(0xffffffffu, bi, o);
                if (ov > bv || (ov == bv && oi < bi)) { bv = ov; bi = oi; }
            }
            if (lane == 0) { redf[wid] = bv; redi[wid] = bi; }
            __syncthreads();
            if (tt == 0) {
                float v0 = redf[2 * g64];     int i0 = redi[2 * g64];
                float v1 = redf[2 * g64 + 1]; int i1 = redi[2 * g64 + 1];
                s_idx[g64] = (v1 > v0 || (v1 == v0 && i1 < i0)) ? i1 : i0;
            }
            __syncthreads();
        }
        const int off = s_idx[g64] - 127;

        // ================= x_aug, softmax attention, x_attn =================
        {
            int d0 = tt, d1 = tt + 64;
            int p0 = d0 + off, p1 = d1 + off;
            float xa0 = (p0 >= 0 && p0 < IDIM) ? sx[g64][p0] : 0.f;
            float xa1 = (p1 >= 0 && p1 < IDIM) ? sx[g64][p1] : 0.f;
            float z0 = xa0 * sy[g64][d0];
            float z1 = xa1 * sy[g64][d1];
            float m = fmaxf(z0, z1);
            for (int o = 16; o > 0; o >>= 1) m = fmaxf(m, __shfl_xor_sync(0xffffffffu, m, o));
            if (lane == 0) redf[wid] = m;
            __syncthreads();
            m = fmaxf(redf[2 * g64], redf[2 * g64 + 1]);
            __syncthreads();
            float e0 = expf(z0 - m), e1 = expf(z1 - m);
            float se = e0 + e1;
            for (int o = 16; o > 0; o >>= 1) se += __shfl_xor_sync(0xffffffffu, se, o);
            if (lane == 0) redf[wid] = se;
            __syncthreads();
            se = redf[2 * g64] + redf[2 * g64 + 1];
            sxa[g64][d0] = xa0 * (e0 / se);
            sxa[g64][d1] = xa1 * (e1 / se);
            __syncthreads();
        }

        // ================= x_ele (reverse shift) and x_res update =================
        {
            int d0 = tt, d1 = tt + 64;
            int q0 = d0 - off, q1 = d1 - off;
            float xe0 = (q0 >= 0 && q0 < IDIM) ? sxa[g64][q0] : 0.f;
            float xe1 = (q1 >= 0 && q1 < IDIM) ? sxa[g64][q1] : 0.f;
            sx[g64][d0] -= xe0;
            sx[g64][d1] -= xe1;
            // sx not read again until next iteration (syncs in between)
        }

        // ================= MLP layer 1 (coalesced transposed weights) =========
        // thread: channels [it*CDIM + 4*m1_tc .. +3], token m1_g
        {
            const float* wp = g_w1t + it * CDIM + m1_tc * 4;
            const float* xp = sxa[m1_g];
            float a0 = 0.f, a1 = 0.f, a2 = 0.f, a3 = 0.f;
            #pragma unroll 4
            for (int d = 0; d < IDIM; d++) {
                float4 w = *(const float4*)(wp + (size_t)d * HDIM);
                float  a = xp[d];
                a0 += w.x * a; a1 += w.y * a; a2 += w.z * a; a3 += w.w * a;
            }
            float4 bb = *(const float4*)(b1 + it * CDIM + m1_tc * 4);
            float* hp = &sh[m1_g][m1_tc * 4];
            *(float4*)hp = make_float4(a0 + bb.x, a1 + bb.y, a2 + bb.z, a3 + bb.w);
            __syncthreads();
        }

        // ================= MLP layer 2 + loss + y_res update ==================
        {
            const float* wp = g_w2t + (size_t)(it * CDIM + m2_half * 128) * IDIM + m2_og * 4;
            const float* hp = &sh[m2_g][m2_half * 128];
            float a0 = 0.f, a1 = 0.f, a2 = 0.f, a3 = 0.f;
            #pragma unroll 4
            for (int k = 0; k < 128; k++) {
                float4 w = *(const float4*)(wp + (size_t)k * IDIM);
                float  h = hp[k];
                a0 += w.x * h; a1 += w.y * h; a2 += w.z * h; a3 += w.w * h;
            }
            if (m2_half == 1)
                *(float4*)&sye[m2_g][m2_og * 4] = make_float4(a0, a1, a2, a3);
            __syncthreads();
            if (m2_half == 0) {
                float4 pb = *(const float4*)&sye[m2_g][m2_og * 4];
                float4 bb = *(const float4*)(b2 + m2_og * 4);
                float4 yr = *(const float4*)&sy[m2_g][m2_og * 4];
                float ye0 = a0 + pb.x + bb.x;
                float ye1 = a1 + pb.y + bb.y;
                float ye2 = a2 + pb.z + bb.z;
                float ye3 = a3 + pb.w + bb.w;
                float d0 = ye0 - yr.x, d1 = ye1 - yr.y, d2 = ye2 - yr.z, d3 = ye3 - yr.w;
                const unsigned char* mp = &smsk[m2_g][m2_og * 4];
                if (!mp[0]) lossAcc += d0 * d0;
                if (!mp[1]) lossAcc += d1 * d1;
                if (!mp[2]) lossAcc += d2 * d2;
                if (!mp[3]) lossAcc += d3 * d3;
                *(float4*)&sy[m2_g][m2_og * 4] =
                    make_float4(yr.x - ye0, yr.y - ye1, yr.z - ye2, yr.w - ye3);
            }
            __syncthreads();
        }
    }

    // ---- deterministic per-block loss reduction ----
    for (int o = 16; o > 0; o >>= 1) lossAcc += __shfl_xor_sync(0xffffffffu, lossAcc, o);
    if (lane == 0) redf[wid] = lossAcc;
    __syncthreads();
    if (tid == 0) {
        float s = 0.f;
        for (int w = 0; w < 8; w++) s += redf[w];
        g_partS[blk] = s;
        __threadfence();
        unsigned int t = atomicAdd(&g_ticket, 1u);
        sIsLast = (t == NBLK - 1) ? 1 : 0;
    }
    __syncthreads();

    // ---- last block: fused finalize (deterministic fixed-order) ----
    if (sIsLast) {
        __threadfence();
        volatile float* vS = g_partS;
        volatile int*   vC = g_partC;
        float s = vS[tid] + vS[tid + 256];
        int   c = vC[tid] + vC[tid + 256];
        for (int o = 16; o > 0; o >>= 1) {
            s += __shfl_xor_sync(0xffffffffu, s, o);
            c += __shfl_xor_sync(0xffffffffu, c, o);
        }
        if (lane == 0) { redf[wid] = s; redi[wid] = c; }
        __syncthreads();
        if (tid == 0) {
            float S = 0.f; int C = 0;
            for (int w = 0; w < 8; w++) { S += redf[w]; C += redi[w]; }
            out[0] = S / (4.0f * (float)C);   // mean over NIT of (sum_sq / denom)
            g_ticket = 0;                      // reset for next graph replay
        }
    }
}

extern "C" void kernel_launch(void* const* d_in, const int* in_sizes, int n_in,
                              void* d_out, int out_size)
{
    const float* x  = (const float*)d_in[0];
    const float* y  = (const float*)d_in[1];
    const float* w1 = (const float*)d_in[2];
    const float* b1 = (const float*)d_in[3];
    const float* w2 = (const float*)d_in[4];
    const float* b2 = (const float*)d_in[5];

    dim3 tb(32, 8);
    transpose_w1<<<dim3(IDIM / 32, HDIM / 32), tb>>>(w1);   // 4 x 32
    transpose_w2<<<dim3(HDIM / 32, IDIM / 32), tb>>>(w2);   // 32 x 4
    fwd_kernel<<<NBLK, NT>>>(x, y, b1, b2, (float*)d_out);
}